// round 3
// baseline (speedup 1.0000x reference)
#include <cuda_runtime.h>
#include <stdint.h>

#define D_    64
#define H_    32
#define W_    32
#define CIN_  128
#define COUT_ 128
#define KTAPS 9
#define NPIX  (D_*H_*W_)     // 65536
#define KOFF  1152
#define ROWS  4

// -------- scratch (no allocations allowed) --------
__device__ uint4 g_xb[NPIX];            // packed x bits: 128 bits / pixel
__device__ int   g_px[NPIX];            // per-pixel popcount
__device__ int   g_sx[NPIX];            // 3x3 (zero-padded) sum of g_px
__device__ uint4 g_wb[D_*KTAPS*COUT_];  // packed w bits per (d,tap,cout)
__device__ int   g_sw[D_*COUT_];        // filter popcounts
__device__ int   g_x_mode;              // 0=uint8, 1=int32, 2=float32, 3=bf16

// bytes of v are 0/1: returns b0 | b1<<1 | b2<<2 | b3<<3
__device__ __forceinline__ uint32_t nib(uint32_t v){
    return (v | (v >> 7) | (v >> 14) | (v >> 21)) & 0xFu;
}

// Dtype probe on first 4096 bytes. Signatures for 0/1-valued data:
//   uint8 : bytes all in {0,1}, nonzeros at arbitrary positions
//   int32 : bytes all in {0,1}, nonzero ONLY at pos%4==0
//   float32 (1.0f = 00 00 80 3F): bytes >1 present, byte at pos%4==1 never 0x3F
//   bf16    (1.0  =       80 3F): bytes >1 present, 0x3F appears at pos%4==1
__global__ void detect_kernel(const uint8_t* __restrict__ x){
    int gt1 = 0, nz_off = 0, bf = 0;
    for (int i = threadIdx.x; i < 4096; i += blockDim.x){
        uint8_t b = x[i];
        if (b > 1) gt1 = 1;
        if ((i & 3) != 0 && b != 0) nz_off = 1;
        if ((i & 3) == 1 && b == 0x3F) bf = 1;
    }
    gt1    = __syncthreads_or(gt1);
    nz_off = __syncthreads_or(nz_off);
    bf     = __syncthreads_or(bf);
    if (threadIdx.x == 0)
        g_x_mode = (!gt1) ? (nz_off ? 0 : 1) : (bf ? 3 : 2);
}

// One thread per pixel: pack 128 channel values -> 4 uint32 words + popcount.
__global__ void pack_x_kernel(const uint8_t* __restrict__ x){
    int p = blockIdx.x * blockDim.x + threadIdx.x;
    if (p >= NPIX) return;
    uint32_t wd[4]; int s = 0;
    int mode = g_x_mode;
    if (mode == 0){                       // uint8 bool
        const uint4* px = reinterpret_cast<const uint4*>(x) + (size_t)p * 8;
        #pragma unroll
        for (int k = 0; k < 4; k++){
            uint4 a = px[2*k], b = px[2*k+1];
            uint32_t v = nib(a.x)        | (nib(a.y) << 4)  | (nib(a.z) << 8)  | (nib(a.w) << 12)
                       | (nib(b.x) << 16)| (nib(b.y) << 20) | (nib(b.z) << 24) | (nib(b.w) << 28);
            wd[k] = v; s += __popc(v);
        }
    } else if (mode == 1){                // int32 0/1
        const uint4* pi = reinterpret_cast<const uint4*>(x) + (size_t)p * 32;
        #pragma unroll
        for (int k = 0; k < 4; k++){
            uint32_t v = 0;
            #pragma unroll
            for (int q = 0; q < 8; q++){
                uint4 a = pi[k*8 + q];
                v |= (a.x ? 1u : 0u) << (q*4 + 0);
                v |= (a.y ? 1u : 0u) << (q*4 + 1);
                v |= (a.z ? 1u : 0u) << (q*4 + 2);
                v |= (a.w ? 1u : 0u) << (q*4 + 3);
            }
            wd[k] = v; s += __popc(v);
        }
    } else if (mode == 2){                // float32 0/1
        const float4* pf = reinterpret_cast<const float4*>(x) + (size_t)p * 32;
        #pragma unroll
        for (int k = 0; k < 4; k++){
            uint32_t v = 0;
            #pragma unroll
            for (int q = 0; q < 8; q++){
                float4 f = pf[k*8 + q];
                v |= (f.x != 0.0f ? 1u : 0u) << (q*4 + 0);
                v |= (f.y != 0.0f ? 1u : 0u) << (q*4 + 1);
                v |= (f.z != 0.0f ? 1u : 0u) << (q*4 + 2);
                v |= (f.w != 0.0f ? 1u : 0u) << (q*4 + 3);
            }
            wd[k] = v; s += __popc(v);
        }
    } else {                              // bf16 0/1 (2 bytes each)
        const uint4* pb = reinterpret_cast<const uint4*>(x) + (size_t)p * 16;
        #pragma unroll
        for (int k = 0; k < 4; k++){
            uint32_t v = 0;
            #pragma unroll
            for (int q = 0; q < 4; q++){
                uint4 a = pb[k*4 + q];   // 8 bf16 values
                uint32_t r[4] = {a.x, a.y, a.z, a.w};
                #pragma unroll
                for (int e = 0; e < 4; e++){
                    v |= ((r[e] & 0x7FFFu)      ? 1u : 0u) << (q*8 + e*2 + 0);
                    v |= ((r[e] & 0x7FFF0000u)  ? 1u : 0u) << (q*8 + e*2 + 1);
                }
            }
            wd[k] = v; s += __popc(v);
        }
    }
    g_xb[p] = make_uint4(wd[0], wd[1], wd[2], wd[3]);
    g_px[p] = s;
}

// One block per (d,tap): transpose 128(cin) x 128(cout) float tile via smem,
// pack cin bits per cout. Coalesced global reads, conflict-free smem.
__global__ void pack_w_kernel(const float* __restrict__ w){
    __shared__ float tile[32][129];
    int dt  = blockIdx.x;          // d*9 + tap
    int tid = threadIdx.x;         // 256 threads
    const float* wp = w + (size_t)dt * (CIN_ * COUT_);
    uint32_t wd[4];
    #pragma unroll
    for (int chunk = 0; chunk < 4; chunk++){
        __syncthreads();
        #pragma unroll
        for (int e = 0; e < 16; e++){
            int idx = e * 256 + tid;                 // 32 cin-rows x 128 cout
            tile[idx >> 7][idx & 127] = wp[chunk * 4096 + idx];
        }
        __syncthreads();
        if (tid < 128){
            uint32_t v = 0;
            #pragma unroll
            for (int r = 0; r < 32; r++)
                v |= (tile[r][tid] != 0.0f ? 1u : 0u) << r;
            wd[chunk] = v;
        }
    }
    if (tid < 128)
        g_wb[dt * COUT_ + tid] = make_uint4(wd[0], wd[1], wd[2], wd[3]);
}

// sw[d][co] = popcount of the whole 3x3x128 filter
__global__ void sums_kernel(){
    int i = blockIdx.x * blockDim.x + threadIdx.x;
    if (i >= D_ * COUT_) return;
    int d = i >> 7, co = i & 127;
    int s = 0;
    #pragma unroll
    for (int t = 0; t < KTAPS; t++){
        uint4 v = g_wb[(d * KTAPS + t) * COUT_ + co];
        s += __popc(v.x) + __popc(v.y) + __popc(v.z) + __popc(v.w);
    }
    g_sw[i] = s;
}

// sx[d][h][w] = 3x3 (zero-padded) neighborhood sum of per-pixel popcounts
__global__ void sx_kernel(){
    int p = blockIdx.x * blockDim.x + threadIdx.x;
    if (p >= NPIX) return;
    int wc = p & 31, hc = (p >> 5) & 31, d = p >> 10;
    int s = 0;
    #pragma unroll
    for (int di = -1; di <= 1; di++){
        int hh = hc + di; if (hh < 0 || hh >= H_) continue;
        #pragma unroll
        for (int dj = -1; dj <= 1; dj++){
            int ww = wc + dj; if (ww < 0 || ww >= W_) continue;
            s += g_px[(d * H_ + hh) * W_ + ww];
        }
    }
    g_sx[p] = s;
}

// Main conv: block = (d, 4-row band). Thread co keeps its 36 w-words in
// registers; x tile sits in smem (warp-broadcast LDS.128); STG fully
// coalesced (consecutive lanes = consecutive cout).
__global__ __launch_bounds__(256)
void conv_kernel(float* __restrict__ out){
    __shared__ uint4 xs[ROWS + 2][W_ + 2];
    __shared__ int   sxs[ROWS][W_];
    int tid = threadIdx.x;
    int co  = tid & 127;
    int g   = tid >> 7;            // 2 pixel groups
    int d   = blockIdx.y;
    int r0  = blockIdx.x * ROWS;

    // x tile with zero halo
    for (int i = tid; i < (ROWS + 2) * (W_ + 2); i += 256){
        int rr = i / (W_ + 2), cc = i % (W_ + 2);
        int hh = r0 - 1 + rr, ww = cc - 1;
        uint4 v = make_uint4(0u, 0u, 0u, 0u);
        if (hh >= 0 && hh < H_ && ww >= 0 && ww < W_)
            v = g_xb[(d * H_ + hh) * W_ + ww];
        xs[rr][cc] = v;
    }
    for (int i = tid; i < ROWS * W_; i += 256)
        sxs[i >> 5][i & 31] = g_sx[(d * H_ + r0 + (i >> 5)) * W_ + (i & 31)];

    uint4 wr[9];
    #pragma unroll
    for (int t = 0; t < 9; t++)
        wr[t] = g_wb[(d * KTAPS + t) * COUT_ + co];
    int bias = KOFF - 2 * g_sw[d * COUT_ + co];
    __syncthreads();

    float* outp = out + ((size_t)(d * H_ + r0) * W_) * COUT_ + co;
    for (int p = g; p < ROWS * W_; p += 2){
        int pr = p >> 5, pc = p & 31;
        int acc = 0;
        #pragma unroll
        for (int t = 0; t < 9; t++){
            uint4 xv = xs[pr + t / 3][pc + t % 3];
            acc += __popc(xv.x & wr[t].x);
            acc += __popc(xv.y & wr[t].y);
            acc += __popc(xv.z & wr[t].z);
            acc += __popc(xv.w & wr[t].w);
        }
        int val = 4 * acc - 2 * sxs[pr][pc] + bias;
        outp[(size_t)p * COUT_] = (float)val;
    }
}

extern "C" void kernel_launch(void* const* d_in, const int* in_sizes, int n_in,
                              void* d_out, int out_size){
    const void* in0 = d_in[0];
    const void* in1 = d_in[1];
    // defensive: identify x (8388608 elems) vs w (9437184 elems) by size
    if (in_sizes[0] == D_*KTAPS*CIN_*COUT_) { const void* t = in0; in0 = in1; in1 = t; }
    const uint8_t* x = (const uint8_t*)in0;
    const float*   w = (const float*)in1;
    float* out = (float*)d_out;

    detect_kernel<<<1, 256>>>(x);
    pack_x_kernel<<<NPIX / 256, 256>>>(x);
    pack_w_kernel<<<D_ * KTAPS, 256>>>(w);
    sums_kernel<<<(D_ * COUT_ + 255) / 256, 256>>>();
    sx_kernel<<<NPIX / 256, 256>>>();
    conv_kernel<<<dim3(H_ / ROWS, D_), 256>>>(out);
}

// round 4
// speedup vs baseline: 1.5740x; 1.5740x over previous
#include <cuda_runtime.h>
#include <stdint.h>

#define D_    64
#define H_    32
#define W_    32
#define CIN_  128
#define COUT_ 128
#define KTAPS 9
#define NPIX  (D_*H_*W_)     // 65536
#define KOFF  1152
#define ROWS  4

// -------- scratch (no allocations allowed) --------
__device__ uint4 g_xb[NPIX];            // packed x bits: 128 bits / pixel
__device__ uint4 g_wb[D_*KTAPS*COUT_];  // packed w bits per (d,tap,cout)
__device__ int   g_x_mode;              // 0=uint8, 1=int32, 2=float32, 3=bf16

// bytes of v are 0/1: returns b0 | b1<<1 | b2<<2 | b3<<3
__device__ __forceinline__ uint32_t nib(uint32_t v){
    return (v | (v >> 7) | (v >> 14) | (v >> 21)) & 0xFu;
}

// Dtype probe on first 4096 bytes (one warp, vectorized).
//   uint8 : bytes all in {0,1}, nonzeros at arbitrary positions
//   int32 : bytes all in {0,1}, nonzero ONLY at pos%4==0
//   float32 (1.0f = 00 00 80 3F): bytes >1, byte at pos%4==1 never 0x3F
//   bf16    (1.0  =       80 3F): bytes >1, 0x3F appears at pos%4==1
__global__ void detect_kernel(const uint8_t* __restrict__ x){
    const uint4* p4 = reinterpret_cast<const uint4*>(x);
    int gt1 = 0, nz_off = 0, bf = 0;
    for (int i = threadIdx.x; i < 256; i += 32){
        uint4 a = p4[i];
        uint32_t r[4] = {a.x, a.y, a.z, a.w};
        #pragma unroll
        for (int e = 0; e < 4; e++){
            uint32_t v = r[e];
            if ((v & 0xFEFEFEFEu))             gt1 = 1;     // any byte >1
            if ((v & 0xFFFFFF00u))             nz_off = 1;  // nonzero off-pos
            if (((v >> 8) & 0xFF) == 0x3Fu)    bf = 1;      // byte1 == 0x3F
        }
    }
    gt1    = __reduce_or_sync(0xFFFFFFFFu, gt1);
    nz_off = __reduce_or_sync(0xFFFFFFFFu, nz_off);
    bf     = __reduce_or_sync(0xFFFFFFFFu, bf);
    if (threadIdx.x == 0)
        g_x_mode = (!gt1) ? (nz_off ? 0 : 1) : (bf ? 3 : 2);
}

// One thread per pixel: pack 128 channel values -> 4 uint32 words.
__global__ void pack_x_kernel(const uint8_t* __restrict__ x){
    int p = blockIdx.x * blockDim.x + threadIdx.x;
    if (p >= NPIX) return;
    uint32_t wd[4];
    int mode = g_x_mode;
    if (mode == 1){                       // int32 0/1 (observed in practice)
        const uint4* pi = reinterpret_cast<const uint4*>(x) + (size_t)p * 32;
        #pragma unroll
        for (int k = 0; k < 4; k++){
            uint32_t v = 0;
            #pragma unroll
            for (int q = 0; q < 8; q++){
                uint4 a = pi[k*8 + q];
                v |= (a.x ? 1u : 0u) << (q*4 + 0);
                v |= (a.y ? 1u : 0u) << (q*4 + 1);
                v |= (a.z ? 1u : 0u) << (q*4 + 2);
                v |= (a.w ? 1u : 0u) << (q*4 + 3);
            }
            wd[k] = v;
        }
    } else if (mode == 0){                // uint8 bool
        const uint4* px = reinterpret_cast<const uint4*>(x) + (size_t)p * 8;
        #pragma unroll
        for (int k = 0; k < 4; k++){
            uint4 a = px[2*k], b = px[2*k+1];
            wd[k] = nib(a.x)        | (nib(a.y) << 4)  | (nib(a.z) << 8)  | (nib(a.w) << 12)
                  | (nib(b.x) << 16)| (nib(b.y) << 20) | (nib(b.z) << 24) | (nib(b.w) << 28);
        }
    } else if (mode == 2){                // float32 0/1
        const float4* pf = reinterpret_cast<const float4*>(x) + (size_t)p * 32;
        #pragma unroll
        for (int k = 0; k < 4; k++){
            uint32_t v = 0;
            #pragma unroll
            for (int q = 0; q < 8; q++){
                float4 f = pf[k*8 + q];
                v |= (f.x != 0.0f ? 1u : 0u) << (q*4 + 0);
                v |= (f.y != 0.0f ? 1u : 0u) << (q*4 + 1);
                v |= (f.z != 0.0f ? 1u : 0u) << (q*4 + 2);
                v |= (f.w != 0.0f ? 1u : 0u) << (q*4 + 3);
            }
            wd[k] = v;
        }
    } else {                              // bf16 0/1
        const uint4* pb = reinterpret_cast<const uint4*>(x) + (size_t)p * 16;
        #pragma unroll
        for (int k = 0; k < 4; k++){
            uint32_t v = 0;
            #pragma unroll
            for (int q = 0; q < 4; q++){
                uint4 a = pb[k*4 + q];
                uint32_t r[4] = {a.x, a.y, a.z, a.w};
                #pragma unroll
                for (int e = 0; e < 4; e++){
                    v |= ((r[e] & 0x7FFFu)     ? 1u : 0u) << (q*8 + e*2 + 0);
                    v |= ((r[e] & 0x7FFF0000u) ? 1u : 0u) << (q*8 + e*2 + 1);
                }
            }
            wd[k] = v;
        }
    }
    g_xb[p] = make_uint4(wd[0], wd[1], wd[2], wd[3]);
}

// One block per (d,tap): coalesced load of 128(cin)x128(cout) float tile via
// smem, then BALLOT across cin-lanes packs 32 bits in one instruction.
__global__ void pack_w_kernel(const float* __restrict__ w){
    __shared__ float    tile[32][129];
    __shared__ uint32_t wword[4][128];
    int dt   = blockIdx.x;          // d*9 + tap
    int tid  = threadIdx.x;         // 256 threads
    int lane = tid & 31, warp = tid >> 5;
    const float* wp = w + (size_t)dt * (CIN_ * COUT_);
    #pragma unroll
    for (int chunk = 0; chunk < 4; chunk++){
        __syncthreads();
        #pragma unroll
        for (int e = 0; e < 16; e++){
            int idx = e * 256 + tid;                 // 32 cin-rows x 128 cout
            tile[idx >> 7][idx & 127] = wp[chunk * 4096 + idx];
        }
        __syncthreads();
        #pragma unroll
        for (int k = 0; k < 16; k++){
            int c = warp * 16 + k;                   // cout; lane = cin bit
            uint32_t b = __ballot_sync(0xFFFFFFFFu, tile[lane][c] != 0.0f);
            if (lane == 0) wword[chunk][c] = b;
        }
    }
    __syncthreads();
    if (tid < 128)
        g_wb[dt * COUT_ + tid] =
            make_uint4(wword[0][tid], wword[1][tid], wword[2][tid], wword[3][tid]);
}

// Fused conv: block = (d, 4-row band). Thread co keeps its 36 w-words in
// registers; bias (sw) computed from those registers; sx computed from
// in-tile popcounts via horizontal 3-sums. Coalesced STG.
__global__ __launch_bounds__(256)
void conv_kernel(float* __restrict__ out){
    __shared__ uint4 xs [ROWS + 2][W_ + 2];
    __shared__ int   pxs[ROWS + 2][W_ + 2];
    __shared__ int   rs [ROWS + 2][W_];
    int tid = threadIdx.x;
    int co  = tid & 127;
    int g   = tid >> 7;            // 2 pixel groups
    int d   = blockIdx.y;
    int r0  = blockIdx.x * ROWS;

    // x tile with zero halo + per-entry popcount
    for (int i = tid; i < (ROWS + 2) * (W_ + 2); i += 256){
        int rr = i / (W_ + 2), cc = i % (W_ + 2);
        int hh = r0 - 1 + rr, ww = cc - 1;
        uint4 v = make_uint4(0u, 0u, 0u, 0u);
        if (hh >= 0 && hh < H_ && (unsigned)ww < W_)
            v = g_xb[(d * H_ + hh) * W_ + ww];
        xs[rr][cc]  = v;
        pxs[rr][cc] = __popc(v.x) + __popc(v.y) + __popc(v.z) + __popc(v.w);
    }

    uint4 wr[9];
    #pragma unroll
    for (int t = 0; t < 9; t++)
        wr[t] = g_wb[(d * KTAPS + t) * COUT_ + co];
    int sw = 0;
    #pragma unroll
    for (int t = 0; t < 9; t++)
        sw += __popc(wr[t].x) + __popc(wr[t].y) + __popc(wr[t].z) + __popc(wr[t].w);
    int bias = KOFF - 2 * sw;
    __syncthreads();

    // horizontal 3-sums of popcounts (reads pxs, one pass)
    for (int i = tid; i < (ROWS + 2) * W_; i += 256){
        int rr = i >> 5, cc = i & 31;
        rs[rr][cc] = pxs[rr][cc] + pxs[rr][cc + 1] + pxs[rr][cc + 2];
    }
    __syncthreads();

    float* outp = out + ((size_t)(d * H_ + r0) * W_) * COUT_ + co;
    #pragma unroll 2
    for (int p = g; p < ROWS * W_; p += 2){
        int pr = p >> 5, pc = p & 31;
        int acc = 0;
        #pragma unroll
        for (int t = 0; t < 9; t++){
            uint4 xv = xs[pr + t / 3][pc + t % 3];
            acc += __popc(xv.x & wr[t].x);
            acc += __popc(xv.y & wr[t].y);
            acc += __popc(xv.z & wr[t].z);
            acc += __popc(xv.w & wr[t].w);
        }
        int sx = rs[pr][pc] + rs[pr + 1][pc] + rs[pr + 2][pc];
        outp[(size_t)p * COUT_] = (float)(4 * acc - 2 * sx + bias);
    }
}

extern "C" void kernel_launch(void* const* d_in, const int* in_sizes, int n_in,
                              void* d_out, int out_size){
    const void* in0 = d_in[0];
    const void* in1 = d_in[1];
    // defensive: identify x vs w (9437184 elems) by size
    if (in_sizes[0] == D_*KTAPS*CIN_*COUT_) { const void* t = in0; in0 = in1; in1 = t; }
    const uint8_t* x = (const uint8_t*)in0;
    const float*   w = (const float*)in1;
    float* out = (float*)d_out;

    detect_kernel<<<1, 32>>>(x);
    pack_x_kernel<<<NPIX / 256, 256>>>(x);
    pack_w_kernel<<<D_ * KTAPS, 256>>>(w);
    conv_kernel<<<dim3(H_ / ROWS, D_), 256>>>(out);
}